// round 1
// baseline (speedup 1.0000x reference)
#include <cuda_runtime.h>
#include <math.h>

// Problem constants
#define NB   64          // bins
#define G    8           // grid per axis
#define NT   512         // tiles = 8^3
#define TS   16          // tile side
#define DIM  128         // volume side
#define NVOX (128*128*128)
#define VPT  4096.0f
#define CLIP_LIM 256.0f  // floor(4.0*4096/64)

// Static device scratch (no allocation allowed)
__device__ float    g_cdf[NB * NT];           // [n][i][j][k]  (i,j,k = tile coords), 128 KB
__device__ float    g_P[DIM * NB * G * G];    // [d][n][j][k], 2 MB
__device__ float    g_M[DIM * G];             // shared axis matrix (D=H=W, g same)
__device__ unsigned g_minmax[2];              // encoded float min/max

// ---------------------------------------------------------------- helpers
__device__ __forceinline__ float bspline5(float x) {
    float t = fabsf(x);
    float t2 = t * t, t3 = t2 * t, t4 = t2 * t2, t5 = t4 * t;
    if (t < 1.0f)
        return 11.0f/20.0f - 0.5f*t2 + 0.25f*t4 - t5*(1.0f/12.0f);
    if (t < 2.0f)
        return 17.0f/40.0f + t*(5.0f/8.0f) - t2*(7.0f/4.0f) + t3*(5.0f/4.0f)
             - t4*(3.0f/8.0f) + t5*(1.0f/24.0f);
    if (t < 3.0f) {
        float u = 3.0f - t;
        float u2 = u * u;
        return u2 * u2 * u * (1.0f/120.0f);
    }
    return 0.0f;
}

__device__ __forceinline__ int reflect_dct2(int i, int n) {
    int m = i % (2 * n);
    if (m < 0) m += 2 * n;
    return (m < n) ? m : (2 * n - 1 - m);
}

// Monotone encoding of float -> unsigned for atomic min/max
__device__ __forceinline__ unsigned fenc(float f) {
    unsigned u = __float_as_uint(f);
    return (u & 0x80000000u) ? ~u : (u | 0x80000000u);
}
__device__ __forceinline__ float fdec(unsigned e) {
    unsigned u = (e & 0x80000000u) ? (e & 0x7FFFFFFFu) : ~e;
    return __uint_as_float(u);
}

// ---------------------------------------------------------------- K0: axis matrix + minmax reset
__global__ void k0_matrix() {
    int s = threadIdx.x;
    if (s == 0) { g_minmax[0] = 0xFFFFFFFFu; g_minmax[1] = 0u; }
    if (s < DIM) {
        // linspace(-0.5 - 0.25/8, 8 - 1 + 0.5 + 0.25/8, 128)
        const float start = -0.53125f;
        const float step  = 8.0625f / 127.0f;
        float c = start + (float)s * step;
        float row[G];
        #pragma unroll
        for (int i = 0; i < G; i++) row[i] = 0.0f;
        int base = (int)floorf(c) - 2;
        #pragma unroll
        for (int t = 0; t < 6; t++) {
            int tap = base + t;
            float w = bspline5(c - (float)tap);
            row[reflect_dct2(tap, G)] += w;
        }
        #pragma unroll
        for (int i = 0; i < G; i++) g_M[s * G + i] = row[i];
    }
}

// ---------------------------------------------------------------- K1: per-tile KDE hist + clip + cdf
__global__ void k1_hist(const float* __restrict__ x) {
    __shared__ float hist[NB];
    int tile = blockIdx.x;
    int ti = tile >> 6, tj = (tile >> 3) & 7, tk = tile & 7;
    int tid = threadIdx.x;
    if (tid < NB) hist[tid] = 0.0f;
    __syncthreads();

    // 4096 voxels / 256 threads: thread handles one (h,w) in-tile pos, loops d
    int b = tid >> 4;      // h within tile
    int cc = tid & 15;     // w within tile
    int d0 = ti * TS, h0 = tj * TS, w0 = tk * TS;
    const float inv63 = 1.0f / 63.0f;
    for (int a = 0; a < TS; a++) {
        float v = x[((d0 + a) * DIM + (h0 + b)) * DIM + (w0 + cc)];
        float pos = v * 63.0f;
        int n0 = (int)floorf(pos);
        if (n0 > 62) n0 = 62;
        if (n0 < 0)  n0 = 0;
        // Only the two straddling bins survive float32 underflow of the Gaussian
        float u0 = (v - (float)n0 * inv63) * 1000.0f;
        float u1 = (v - (float)(n0 + 1) * inv63) * 1000.0f;
        atomicAdd(&hist[n0],     expf(-0.5f * u0 * u0));
        atomicAdd(&hist[n0 + 1], expf(-0.5f * u1 * u1));
    }
    __syncthreads();

    if (tid == 0) {
        float pdf[NB];
        float s = 0.0f;
        for (int n = 0; n < NB; n++) { pdf[n] = hist[n] * (1.0f / 4096.0f); s += pdf[n]; }
        float inv = 1.0f / (s + 1e-10f);
        float tot = 0.0f;
        float h2[NB];
        for (int n = 0; n < NB; n++) {
            float hh = fminf(pdf[n] * inv * 4096.0f, CLIP_LIM);
            h2[n] = hh;
            tot += hh;
        }
        float clipped  = 4096.0f - tot;
        float residual = fmodf(clipped, 64.0f);
        float redist   = (clipped - residual) * (1.0f / 64.0f);
        float c = 0.0f;
        int tbase = ti * 64 + tj * 8 + tk;
        for (int n = 0; n < NB; n++) {
            float hv = h2[n] + redist + (((float)n < residual) ? 1.0f : 0.0f);
            c += hv;
            g_cdf[n * NT + tbase] = c * (63.0f / 4096.0f);
        }
    }
}

// ---------------------------------------------------------------- K2: P[d][n][j][k] = sum_i Md[d,i]*cdf[n,i,j,k]
__global__ void k2_P() {
    int idx = blockIdx.x * blockDim.x + threadIdx.x;   // [d][n][j][k]
    int k = idx & 7;
    int j = (idx >> 3) & 7;
    int n = (idx >> 6) & 63;
    int d = idx >> 12;
    float acc = 0.0f;
    #pragma unroll
    for (int i = 0; i < 8; i++)
        acc += g_M[d * 8 + i] * g_cdf[n * NT + i * 64 + j * 8 + k];
    g_P[idx] = acc;
}

// ---------------------------------------------------------------- K3: fused h/w interpolation + bin-axis spline
// grid: (4, 128): blockIdx.y = d slice, blockIdx.x = h quarter (32 rows)
// block: 256 threads = 2 h-rows x 128 w per iteration
__global__ void k3_final(const float* __restrict__ x, float* __restrict__ out) {
    __shared__ __align__(16) float sP[NB * G * G];   // 16 KB, P for this d
    __shared__ __align__(16) float sM[DIM * G];      // 4 KB, axis matrix
    __shared__ __align__(16) float sR[2][NB][8];     // 4 KB, per-h-row contracted cdf

    int d  = blockIdx.y;
    int hb = blockIdx.x * 32;
    int tid = threadIdx.x;

    for (int i = tid; i < NB * G * G; i += 256) sP[i] = g_P[d * NB * G * G + i];
    for (int i = tid; i < DIM * G; i += 256)    sM[i] = g_M[i];
    __syncthreads();

    int hsub = tid >> 7;        // 0 or 1
    int w    = tid & 127;
    float mw[8];
    #pragma unroll
    for (int k = 0; k < 8; k++) mw[k] = sM[w * 8 + k];

    float vmin =  3.0e38f, vmax = -3.0e38f;

    for (int h0 = 0; h0 < 32; h0 += 2) {
        int h = hb + h0 + hsub;

        // Build R[hsub][n][k] = sum_j Mh[h,j] * P[n,j,k]  (512 entries, 128 threads -> 4 each)
        {
            int e0 = (tid & 127) * 4;
            int n  = e0 >> 3;
            int k0 = e0 & 7;       // 0 or 4
            float4 acc = make_float4(0.f, 0.f, 0.f, 0.f);
            #pragma unroll
            for (int j = 0; j < 8; j++) {
                float m = sM[h * 8 + j];
                float4 p = *(const float4*)&sP[n * 64 + j * 8 + k0];
                acc.x += m * p.x; acc.y += m * p.y; acc.z += m * p.z; acc.w += m * p.w;
            }
            *(float4*)&sR[hsub][n][k0] = acc;
        }
        __syncthreads();

        // Per-voxel: quintic spline along bin axis over 6 taps
        float v  = x[(d * DIM + h) * DIM + w];
        float cb = v * 63.0f;
        int base = (int)floorf(cb) - 2;
        float acc = 0.0f;
        #pragma unroll
        for (int t = 0; t < 6; t++) {
            int tap  = base + t;
            float wb = bspline5(cb - (float)tap);
            int n    = reflect_dct2(tap, NB);
            const float* R = sR[hsub][n];
            float s = 0.0f;
            #pragma unroll
            for (int k = 0; k < 8; k++) s += mw[k] * R[k];
            acc += wb * s;
        }
        out[(d * DIM + h) * DIM + w] = acc;
        vmin = fminf(vmin, acc);
        vmax = fmaxf(vmax, acc);
        __syncthreads();
    }

    // Warp-level min/max reduce, one atomic per warp
    #pragma unroll
    for (int off = 16; off > 0; off >>= 1) {
        vmin = fminf(vmin, __shfl_xor_sync(0xFFFFFFFFu, vmin, off));
        vmax = fmaxf(vmax, __shfl_xor_sync(0xFFFFFFFFu, vmax, off));
    }
    if ((tid & 31) == 0) {
        atomicMin(&g_minmax[0], fenc(vmin));
        atomicMax(&g_minmax[1], fenc(vmax));
    }
}

// ---------------------------------------------------------------- K4: global rescale
__global__ void k4_norm(float* __restrict__ out, int n) {
    int i = blockIdx.x * blockDim.x + threadIdx.x;
    float mn = fdec(g_minmax[0]);
    float mx = fdec(g_minmax[1]);
    float denom = mx - mn + 1e-10f;
    if (i < n) out[i] = (out[i] - mn) / denom;
}

// ---------------------------------------------------------------- launch
extern "C" void kernel_launch(void* const* d_in, const int* in_sizes, int n_in,
                              void* d_out, int out_size) {
    const float* x = (const float*)d_in[0];
    float* out = (float*)d_out;

    k0_matrix<<<1, 128>>>();
    k1_hist<<<NT, 256>>>(x);
    k2_P<<<(DIM * NB * G * G) / 256, 256>>>();
    k3_final<<<dim3(4, DIM), 256>>>(x, out);
    k4_norm<<<(out_size + 255) / 256, 256>>>(out, out_size);
}

// round 2
// speedup vs baseline: 1.6054x; 1.6054x over previous
#include <cuda_runtime.h>
#include <math.h>

#define NB   64
#define G    8
#define NT   512
#define TS   16
#define DIM  128
#define CLIP_LIM 256.0f

#define PSTRIDE 68     // padded sP row stride (floats)
#define RSTRIDE 12     // padded sR row stride (floats), 48B: float4-aligned, 3n mod 8 distinct

__device__ float    g_cdf[NB * NT];           // [n][i][j][k]
__device__ float    g_P[DIM * NB * G * G];    // [d][n][j][k]
__device__ float    g_M[DIM * G];
__device__ unsigned g_minmax[2];

// ---------------------------------------------------------------- helpers
__device__ __forceinline__ float bspline5(float x) {
    float t = fabsf(x);
    float t2 = t * t, t3 = t2 * t, t4 = t2 * t2, t5 = t4 * t;
    if (t < 1.0f)
        return 11.0f/20.0f - 0.5f*t2 + 0.25f*t4 - t5*(1.0f/12.0f);
    if (t < 2.0f)
        return 17.0f/40.0f + t*(5.0f/8.0f) - t2*(7.0f/4.0f) + t3*(5.0f/4.0f)
             - t4*(3.0f/8.0f) + t5*(1.0f/24.0f);
    if (t < 3.0f) {
        float u = 3.0f - t;
        float u2 = u * u;
        return u2 * u2 * u * (1.0f/120.0f);
    }
    return 0.0f;
}

__device__ __forceinline__ int reflect_dct2(int i, int n) {
    int m = i % (2 * n);
    if (m < 0) m += 2 * n;
    return (m < n) ? m : (2 * n - 1 - m);
}

__device__ __forceinline__ unsigned fenc(float f) {
    unsigned u = __float_as_uint(f);
    return (u & 0x80000000u) ? ~u : (u | 0x80000000u);
}
__device__ __forceinline__ float fdec(unsigned e) {
    unsigned u = (e & 0x80000000u) ? (e & 0x7FFFFFFFu) : ~e;
    return __uint_as_float(u);
}

// w1 piece of quintic spline, t in [1,2)
__device__ __forceinline__ float w1poly(float t) {
    return 17.0f/40.0f + t*(5.0f/8.0f + t*(-7.0f/4.0f + t*(5.0f/4.0f
         + t*(-3.0f/8.0f + t*(1.0f/24.0f)))));
}
// w0 piece, t in [0,1)
__device__ __forceinline__ float w0poly(float t) {
    float t2 = t * t;
    float t4 = t2 * t2;
    return 11.0f/20.0f - 0.5f*t2 + 0.25f*t4 - t4*t*(1.0f/12.0f);
}

// ---------------------------------------------------------------- K0
__global__ void k0_matrix() {
    int s = threadIdx.x;
    if (s == 0) { g_minmax[0] = 0xFFFFFFFFu; g_minmax[1] = 0u; }
    if (s < DIM) {
        const float start = -0.53125f;
        const float step  = 8.0625f / 127.0f;
        float c = start + (float)s * step;
        float row[G];
        #pragma unroll
        for (int i = 0; i < G; i++) row[i] = 0.0f;
        int base = (int)floorf(c) - 2;
        #pragma unroll
        for (int t = 0; t < 6; t++) {
            int tap = base + t;
            float w = bspline5(c - (float)tap);
            row[reflect_dct2(tap, G)] += w;
        }
        #pragma unroll
        for (int i = 0; i < G; i++) g_M[s * G + i] = row[i];
    }
}

// ---------------------------------------------------------------- K1: per-tile KDE hist + clip + cdf
// Single-nearest-bin KDE: 2nd-nearest bin weight <= exp(-31.5) ~ 2e-14 (negligible).
__global__ void __launch_bounds__(256) k1_hist(const float* __restrict__ x) {
    __shared__ float hist8[8][NB];
    int tile = blockIdx.x;
    int ti = tile >> 6, tj = (tile >> 3) & 7, tk = tile & 7;
    int tid = threadIdx.x;
    int warp = tid >> 5;

    for (int i = tid; i < 8 * NB; i += 256) ((float*)hist8)[i] = 0.0f;
    __syncthreads();

    int b  = tid >> 4;
    int cc = tid & 15;
    int d0 = ti * TS, h0 = tj * TS, w0 = tk * TS;
    for (int a = 0; a < TS; a++) {
        float v = x[((d0 + a) * DIM + (h0 + b)) * DIM + (w0 + cc)];
        float pos = v * 63.0f;
        int nb = __float2int_rn(pos);
        nb = min(63, max(0, nb));
        float u = (pos - (float)nb) * (1000.0f / 63.0f);
        atomicAdd(&hist8[warp][nb], expf(-0.5f * u * u));
    }
    __syncthreads();

    if (tid < NB) {
        float s = 0.0f;
        #pragma unroll
        for (int w = 0; w < 8; w++) s += hist8[w][tid];
        hist8[0][tid] = s;
    }
    __syncthreads();

    if (tid == 0) {
        float s = 0.0f;
        float pdf[NB];
        for (int n = 0; n < NB; n++) { pdf[n] = hist8[0][n] * (1.0f / 4096.0f); s += pdf[n]; }
        float inv = 1.0f / (s + 1e-10f);
        float tot = 0.0f;
        float h2[NB];
        for (int n = 0; n < NB; n++) {
            float hh = fminf(pdf[n] * inv * 4096.0f, CLIP_LIM);
            h2[n] = hh;
            tot += hh;
        }
        float clipped  = 4096.0f - tot;
        float residual = fmodf(clipped, 64.0f);
        float redist   = (clipped - residual) * (1.0f / 64.0f);
        float c = 0.0f;
        int tbase = ti * 64 + tj * 8 + tk;
        for (int n = 0; n < NB; n++) {
            float hv = h2[n] + redist + (((float)n < residual) ? 1.0f : 0.0f);
            c += hv;
            g_cdf[n * NT + tbase] = c * (63.0f / 4096.0f);
        }
    }
}

// ---------------------------------------------------------------- K2: P[d][n][j][k] = sum_i Md[d,i]*cdf[n,i,j,k]
__global__ void k2_P() {
    int idx = blockIdx.x * blockDim.x + threadIdx.x;
    int k = idx & 7;
    int j = (idx >> 3) & 7;
    int n = (idx >> 6) & 63;
    int d = idx >> 12;
    float acc = 0.0f;
    #pragma unroll
    for (int i = 0; i < 8; i++)
        acc += g_M[d * 8 + i] * g_cdf[n * NT + i * 64 + j * 8 + k];
    g_P[idx] = acc;
}

// ---------------------------------------------------------------- K3
// grid (4, 128): y = d slice, x = h quarter (32 rows). 256 thr = 2 h-rows x 128 w.
__global__ void __launch_bounds__(256) k3_final(const float* __restrict__ x,
                                                float* __restrict__ out) {
    __shared__ __align__(16) float sP[NB * PSTRIDE];       // 17408 B (padded rows)
    __shared__ __align__(16) float sMh[32 * G];            // 1 KB: this block's h rows
    __shared__ __align__(16) float sR[2][2][NB * RSTRIDE]; // 12 KB: [buf][hsub]

    int d   = blockIdx.y;
    int hb  = blockIdx.x * 32;
    int tid = threadIdx.x;
    int hsub = tid >> 7;
    int w    = tid & 127;

    // load P (restrided to 68) and this block's 32 rows of M
    for (int i = tid; i < NB * G * G; i += 256) {
        int n = i >> 6, r = i & 63;
        sP[n * PSTRIDE + r] = g_P[d * NB * G * G + i];
    }
    if (tid < 32 * G) sMh[tid] = g_M[hb * G + tid];

    // per-thread w weights straight from global (written by k0)
    float4 mwlo, mwhi;
    {
        const float* m = &g_M[w * G];
        mwlo = make_float4(m[0], m[1], m[2], m[3]);
        mwhi = make_float4(m[4], m[5], m[6], m[7]);
    }
    __syncthreads();

    int lane128 = tid & 127;
    int bn = lane128 & 63;              // build row
    int bk = (lane128 >> 6) << 2;       // build k offset: 0 or 4

    // build R[buf][hsub][n][k] = sum_j Mh[h,j] * P[n,j,k] (conflict-free)
    auto build = [&](int it, int buf) {
        int hl = 2 * it + hsub;
        float4 acc = make_float4(0.f, 0.f, 0.f, 0.f);
        #pragma unroll
        for (int j = 0; j < 8; j++) {
            float m = sMh[hl * 8 + j];
            float4 p = *(const float4*)&sP[bn * PSTRIDE + j * 8 + bk];
            acc.x += m * p.x; acc.y += m * p.y; acc.z += m * p.z; acc.w += m * p.w;
        }
        *(float4*)&sR[buf][hsub][bn * RSTRIDE + bk] = acc;
    };

    build(0, 0);
    __syncthreads();

    float vmin =  3.0e38f, vmax = -3.0e38f;

    for (int it = 0; it < 16; it++) {
        int buf = it & 1;
        if (it + 1 < 16) build(it + 1, buf ^ 1);

        int h = hb + 2 * it + hsub;
        float v  = x[(d * DIM + h) * DIM + w];
        float cb = v * 63.0f;
        float fb = floorf(cb);
        int base = (int)fb - 2;
        float f  = cb - fb;          // [0,1)
        float g1 = 1.0f - f;

        // branch-free quintic weights: tap t has known spline piece
        float f5g = f * f; f5g = f5g * f5g * f;      // f^5
        float g5g = g1 * g1; g5g = g5g * g5g * g1;   // g^5
        float wb[6];
        wb[0] = g5g * (1.0f / 120.0f);
        wb[1] = w1poly(1.0f + f);
        wb[2] = w0poly(f);
        wb[3] = w0poly(g1);
        wb[4] = w1poly(2.0f - f);
        wb[5] = f5g * (1.0f / 120.0f);

        const float* R = sR[buf][hsub];
        float acc = 0.0f;
        #pragma unroll
        for (int t = 0; t < 6; t++) {
            int tap = base + t;
            int n = (tap < 0) ? (-1 - tap) : ((tap > 63) ? (127 - tap) : tap);
            const float4* r4 = (const float4*)(R + n * RSTRIDE);
            float4 a = r4[0], b4 = r4[1];
            float s = mwlo.x * a.x + mwlo.y * a.y + mwlo.z * a.z + mwlo.w * a.w
                    + mwhi.x * b4.x + mwhi.y * b4.y + mwhi.z * b4.z + mwhi.w * b4.w;
            acc = fmaf(wb[t], s, acc);
        }
        out[(d * DIM + h) * DIM + w] = acc;
        vmin = fminf(vmin, acc);
        vmax = fmaxf(vmax, acc);
        __syncthreads();
    }

    #pragma unroll
    for (int off = 16; off > 0; off >>= 1) {
        vmin = fminf(vmin, __shfl_xor_sync(0xFFFFFFFFu, vmin, off));
        vmax = fmaxf(vmax, __shfl_xor_sync(0xFFFFFFFFu, vmax, off));
    }
    if ((tid & 31) == 0) {
        atomicMin(&g_minmax[0], fenc(vmin));
        atomicMax(&g_minmax[1], fenc(vmax));
    }
}

// ---------------------------------------------------------------- K4
__global__ void k4_norm(float4* __restrict__ out, int n4) {
    int i = blockIdx.x * blockDim.x + threadIdx.x;
    float mn = fdec(g_minmax[0]);
    float mx = fdec(g_minmax[1]);
    float inv = 1.0f / (mx - mn + 1e-10f);
    if (i < n4) {
        float4 v = out[i];
        v.x = (v.x - mn) * inv;
        v.y = (v.y - mn) * inv;
        v.z = (v.z - mn) * inv;
        v.w = (v.w - mn) * inv;
        out[i] = v;
    }
}

// ---------------------------------------------------------------- launch
extern "C" void kernel_launch(void* const* d_in, const int* in_sizes, int n_in,
                              void* d_out, int out_size) {
    const float* x = (const float*)d_in[0];
    float* out = (float*)d_out;

    k0_matrix<<<1, 128>>>();
    k1_hist<<<NT, 256>>>(x);
    k2_P<<<(DIM * NB * G * G) / 256, 256>>>();
    k3_final<<<dim3(4, DIM), 256>>>(x, out);
    int n4 = out_size / 4;
    k4_norm<<<(n4 + 255) / 256, 256>>>((float4*)out, n4);
}